// round 6
// baseline (speedup 1.0000x reference)
#include <cuda_runtime.h>
#include <math.h>

#define B_   64
#define N_   4096
#define D_   128
#define E_   512
#define S_   16                 // N-splits per batch
#define GPB  32                 // 8-lane groups per block (256 thr)
#define TSTREAMS (S_*GPB)       // 512 interleaved slot streams per batch

// ---- device scratch (no allocations allowed) ----
// All float4-accessed arrays are explicitly 16B-aligned (R5 crash: default
// 4B alignment of __device__ float arrays broke float4 loads).
// Flags/counters are replay-safe: g_qdone is sticky (data rewritten with
// identical values each launch), g_cdone counts cumulatively (mod-16 test).
__device__ __align__(16) float g_q  [B_*D_];
__device__ __align__(16) float g_qa [B_*D_];
__device__ __align__(16) float g_pacc[B_*S_*D_];
__device__ float g_ps [B_*S_];
__device__ int   g_qdone[B_];
__device__ int   g_cdone[B_];

__global__ void __launch_bounds__(256, 2)
fused_kernel(const float* __restrict__ kb,
             const float* __restrict__ vq,
             const int*   __restrict__ ion,
             const float* __restrict__ Wq,
             const float* __restrict__ bq,
             const float* __restrict__ Wa,
             const float* __restrict__ ba_p,
             float*       __restrict__ out)
{
    const int tid   = threadIdx.x;
    const int warp  = tid >> 5, lane = tid & 31;
    const int bs    = blockIdx.x;
    const int b     = bs >> 4;              // att batch
    const int split = bs & (S_ - 1);
    const int g     = lane >> 3, sub = lane & 7;
    const int gid   = warp * 4 + g;         // 0..31

    __shared__ int   scnt;
    __shared__ float sM, sba;
    __shared__ __align__(16) float sacc[GPB][132];
    __shared__ float ssum[GPB];
    __shared__ int   slast;

    // ---- per-block meta (independent of producers) ----
    if (warp == 0) {
        // int64 vs int32 decode: values in [0,4096); if int64 (LE) every odd
        // 32-bit word of the first 64 is 0. Detection reads stay in first
        // 256B; word 2*b (<=508B) read only when layout is int64 (512B alloc).
        bool oz   = (ion[2*lane + 1] == 0);
        bool is64 = __all_sync(0xffffffffu, oz);
        if (lane == 0) scnt = is64 ? ion[2*b] : ion[b];
    } else if (warp == 1) {
        // M = max(ba + ||Wa||, 0) >= every logit (Cauchy-Schwarz)
        float t = 0.f;
        #pragma unroll
        for (int i = 0; i < 4; i++) { float wv = Wa[i*32 + lane]; t += wv*wv; }
        #pragma unroll
        for (int off = 16; off > 0; off >>= 1)
            t += __shfl_xor_sync(0xffffffffu, t, off);
        if (lane == 0) { float ba = *ba_p; sba = ba; sM = fmaxf(ba + sqrtf(t), 0.f); }
    }

    // ---- producers (blocks 0..63): q/qa for batch `bs`, then release flag.
    //      Producers are wave-1 resident (low bids), so consumers never deadlock.
    if (bs < B_) {
        const float4* v4 = (const float4*)(vq + (size_t)bs * E_);
        float4 v[4];
        #pragma unroll
        for (int j = 0; j < 4; j++) v[j] = v4[j*32 + lane];
        #pragma unroll 2
        for (int t = 0; t < 16; t++) {
            const int d = warp * 16 + t;
            const float4* w4 = (const float4*)(Wq + (size_t)d * E_);
            float a = 0.f;
            #pragma unroll
            for (int j = 0; j < 4; j++) {
                float4 y = w4[j*32 + lane];
                a += v[j].x*y.x + v[j].y*y.y + v[j].z*y.z + v[j].w*y.w;
            }
            #pragma unroll
            for (int off = 16; off > 0; off >>= 1)
                a += __shfl_xor_sync(0xffffffffu, a, off);
            if (lane == 0) {
                float qv = a + bq[d];
                g_q [bs*D_ + d] = qv;
                g_qa[bs*D_ + d] = qv * Wa[d];
            }
        }
        __syncthreads();
        __threadfence();
        if (tid == 0) *((volatile int*)&g_qdone[bs]) = 1;
    }

    // ---- prefetch first two slots (n<512, n+512<1024: always in-bounds),
    //      independent of q -> overlaps the flag spin with DRAM latency.
    const float4* kb4 = (const float4*)(kb + (size_t)b * N_ * D_);
    int n = split * GPB + gid;
    float4 c0[4], c1[4];
    #pragma unroll
    for (int i = 0; i < 4; i++)
        c0[i] = __ldcs(&kb4[(size_t)n*32 + i*8 + sub]);
    #pragma unroll
    for (int i = 0; i < 4; i++)
        c1[i] = __ldcs(&kb4[(size_t)(n + TSTREAMS)*32 + i*8 + sub]);

    // ---- acquire q for our batch ----
    while (*((volatile int*)&g_qdone[b]) == 0) __nanosleep(64);
    __threadfence();
    __syncthreads();          // also publishes scnt/sM/sba

    const int   limit   = (scnt == 0) ? N_ : scnt;
    const bool  uniform = (scnt == 0);
    const float M  = sM;
    const float ba = sba;

    float4 q[4], qa[4];
    #pragma unroll
    for (int i = 0; i < 4; i++) {
        q[i]  = ((const float4*)(g_q  + b*D_))[i*8 + sub];
        qa[i] = ((const float4*)(g_qa + b*D_))[i*8 + sub];
    }

    float  s = 0.f;
    float4 acc[4] = {make_float4(0,0,0,0), make_float4(0,0,0,0),
                     make_float4(0,0,0,0), make_float4(0,0,0,0)};

    // ---- main pass: software-pipelined, clamped streaming loads.
    //      w = exp(L - M): no online max, pure FMA accumulation; invalid
    //      slots get w = 0 exactly (clamped k values are finite -> 0*k = 0).
    while (true) {
        const int  next = n + 2*TSTREAMS;
        const bool more = __any_sync(0xffffffffu, next < limit);

        float4 d0[4], d1[4];
        if (more) {
            const int m0 = min(next,            N_ - 1);
            const int m1 = min(next + TSTREAMS, N_ - 1);
            #pragma unroll
            for (int i = 0; i < 4; i++)
                d0[i] = __ldcs(&kb4[(size_t)m0*32 + i*8 + sub]);
            #pragma unroll
            for (int i = 0; i < 4; i++)
                d1[i] = __ldcs(&kb4[(size_t)m1*32 + i*8 + sub]);
        }

        #pragma unroll
        for (int t = 0; t < 2; t++) {
            float4* k = t ? c1 : c0;
            const bool v = t ? (n + TSTREAMS < limit) : (n < limit);
            float dot = 0.f, nrm = 0.f;
            #pragma unroll
            for (int i = 0; i < 4; i++) {
                float px = k[i].x*q[i].x, py = k[i].y*q[i].y;
                float pz = k[i].z*q[i].z, pw = k[i].w*q[i].w;
                nrm += px*px + py*py + pz*pz + pw*pw;
                dot += k[i].x*qa[i].x + k[i].y*qa[i].y
                     + k[i].z*qa[i].z + k[i].w*qa[i].w;
            }
            #pragma unroll
            for (int off = 4; off > 0; off >>= 1) {
                dot += __shfl_xor_sync(0xffffffffu, dot, off);
                nrm += __shfl_xor_sync(0xffffffffu, nrm, off);
            }
            float L = uniform ? 0.f : (dot * rsqrtf(fmaxf(nrm, 1e-24f)) + ba);
            float w = v ? __expf(L - M) : 0.f;    // L <= M: never overflows
            s += w;
            #pragma unroll
            for (int i = 0; i < 4; i++) {
                acc[i].x += w * k[i].x;  acc[i].y += w * k[i].y;
                acc[i].z += w * k[i].z;  acc[i].w += w * k[i].w;
            }
        }

        if (!more) break;
        #pragma unroll
        for (int i = 0; i < 4; i++) { c0[i] = d0[i]; c1[i] = d1[i]; }
        n = next;
    }

    // ---- merge 32 groups of this CTA (132-stride: aligned, conflict-free) ----
    #pragma unroll
    for (int i = 0; i < 4; i++)
        *(float4*)&sacc[gid][i*32 + sub*4] = acc[i];
    if (sub == 0) ssum[gid] = s;
    __syncthreads();

    if (tid < D_) {
        float a = 0.f;
        #pragma unroll
        for (int j = 0; j < GPB; j++) a += sacc[j][tid];
        g_pacc[bs*D_ + tid] = a;
    } else if (tid == D_) {
        float t = 0.f;
        #pragma unroll
        for (int j = 0; j < GPB; j++) t += ssum[j];
        g_ps[bs] = t;
    }

    // ---- last block per batch combines the 16 split partials ----
    __threadfence();
    __syncthreads();
    if (tid == 0) {
        int old = atomicAdd(&g_cdone[b], 1);     // cumulative across replays
        slast = ((old & (S_ - 1)) == (S_ - 1));
    }
    __syncthreads();
    if (slast) {
        __threadfence();
        if (tid < D_) {
            float ss = 0.f, av = 0.f;
            #pragma unroll
            for (int i = 0; i < S_; i++) {
                ss += __ldcg(&g_ps[b*S_ + i]);
                av += __ldcg(&g_pacc[(b*S_ + i)*D_ + tid]);
            }
            out[b*D_ + tid] = av / ss;           // ss > 0 always (limit >= 1)
        }
    }
}

extern "C" void kernel_launch(void* const* d_in, const int* in_sizes, int n_in,
                              void* d_out, int out_size)
{
    const float* kb  = (const float*)d_in[0];
    const float* vq  = (const float*)d_in[1];
    const int*   ion = (const int*)  d_in[2];   // int32 or int64, auto-detected
    const float* Wq  = (const float*)d_in[3];
    const float* bq  = (const float*)d_in[4];
    const float* Wa  = (const float*)d_in[5];
    const float* ba  = (const float*)d_in[6];
    float* out = (float*)d_out;

    fused_kernel<<<B_ * S_, 256>>>(kb, vq, ion, Wq, bq, Wa, ba, out);
}